// round 7
// baseline (speedup 1.0000x reference)
#include <cuda_runtime.h>

// Problem constants
static const int CDIM = 256;
static const int HWSZ = 1024;   // 32*32
static const int NPIX = 2048;   // B*H*W
static const int PKN  = 256;
static const int CKN  = 256;

// Tiling
#define TP 16
#define TQ 8
#define AS 260   // padded stride for [.][256] fp32 smem rows
#define WS 20    // padded stride for W tile [128][16]
#define KT 16

// Scratch (allocation-free rule: __device__ globals)
__device__ float g_buf0[NPIX * CDIM];
__device__ float g_buf1[NPIX * CDIM];

// ---------------------------------------------------------------------------
// pre_compare layer: OUT[m][n] = act( sum_k A[m][k] * W[n][k] + b[n] )
// MODE 0: x -> buf0 (relu), MODE 1: buf0 -> buf1 (relu), MODE 2: buf1 -> buf0
// ---------------------------------------------------------------------------
template <int MODE>
__global__ void __launch_bounds__(256, 1)
pre_layer_kernel(const float* __restrict__ x,
                 const float* __restrict__ W,
                 const float* __restrict__ bias)
{
    extern __shared__ float sm[];
    float* A_s = sm;                 // [128][AS]
    float* w_s = A_s + 128 * AS;     // [128][WS]

    const int tid = threadIdx.x;
    const int tx = tid & 15;
    const int ty = tid >> 4;
    const int m0 = blockIdx.x * 128;

    const float* in = (MODE == 0) ? x : (MODE == 1 ? g_buf0 : g_buf1);
    float* outp     = (MODE == 1) ? g_buf1 : g_buf0;

    if (MODE == 0) {
        // x layout [B][C][HW]; pixel n = m0+m, consecutive m -> consecutive hw
        for (int e = tid; e < 128 * CDIM; e += 256) {
            int cc = e >> 7;            // 0..255
            int m  = e & 127;
            int n  = m0 + m;
            int b  = n >> 10;
            int hw = n & 1023;
            A_s[m * AS + cc] = in[(b * CDIM + cc) * HWSZ + hw];
        }
    } else {
        for (int e = tid; e < 128 * CDIM; e += 256) {
            int m  = e >> 8;
            int cc = e & 255;
            A_s[m * AS + cc] = in[(m0 + m) * CDIM + cc];
        }
    }
    __syncthreads();

    for (int nc = 0; nc < 2; ++nc) {
        float acc[8][8] = {};
        for (int k0 = 0; k0 < CDIM; k0 += KT) {
            for (int e = tid; e < 128 * KT; e += 256) {
                int n  = e >> 4;
                int kk = e & 15;
                w_s[n * WS + kk] = W[(nc * 128 + n) * CDIM + k0 + kk];
            }
            __syncthreads();
#pragma unroll
            for (int kk = 0; kk < KT; kk += 4) {
                float4 wf[8];
#pragma unroll
                for (int j = 0; j < 8; ++j)
                    wf[j] = *(const float4*)&w_s[(tx + 16 * j) * WS + kk];
#pragma unroll
                for (int i = 0; i < 8; ++i) {
                    float4 a = *(const float4*)&A_s[(ty * 8 + i) * AS + k0 + kk];
#pragma unroll
                    for (int j = 0; j < 8; ++j)
                        acc[i][j] += a.x * wf[j].x + a.y * wf[j].y +
                                     a.z * wf[j].z + a.w * wf[j].w;
                }
            }
            __syncthreads();
        }
#pragma unroll
        for (int i = 0; i < 8; ++i) {
#pragma unroll
            for (int j = 0; j < 8; ++j) {
                int n = nc * 128 + 16 * j + tx;
                float v = acc[i][j] + bias[n];
                if (MODE != 2) v = fmaxf(v, 0.0f);
                outp[(m0 + ty * 8 + i) * CDIM + n] = v;
            }
        }
    }
}

// ---------------------------------------------------------------------------
// Fused edge kernel:
//  per block: 16 p-rows x 8 q-rows (M=128 pairs)
//  GEMM1: g0 = relu(W0 . (xp-xc)^2 + b0)   (xx regenerated from smem)
//  GEMM2: g1 = relu(W1 . g0 + b1), fused out = pow . g1 + pob
// ---------------------------------------------------------------------------
__global__ void __launch_bounds__(256, 1)
edge_kernel(const int* __restrict__ pidx_g,
            const int* __restrict__ cidx_g,
            const float* __restrict__ W0, const float* __restrict__ b0,
            const float* __restrict__ W1, const float* __restrict__ b1,
            const float* __restrict__ pow_g, const float* __restrict__ pob,
            float* __restrict__ out)
{
    extern __shared__ float sm[];
    float* xp_s  = sm;                     // [TP][AS]
    float* xc_s  = xp_s + TP * AS;         // [TQ][AS]
    float* g0_s  = xc_s + TQ * AS;         // [128][AS]
    float* w_s   = g0_s + 128 * AS;        // [128][WS]
    float* pow_s = w_s + 128 * WS;         // [512]

    const int tid = threadIdx.x;
    const int tx = tid & 15;
    const int ty = tid >> 4;
    const int q0 = blockIdx.x * TQ;
    const int p0 = blockIdx.y * TP;
    const int b  = blockIdx.z;

    const float* flat = g_buf0;

    for (int e = tid; e < TP * CDIM; e += 256) {
        int r  = e >> 8;
        int cc = e & 255;
        int idx = pidx_g[b * PKN + p0 + r];
        xp_s[r * AS + cc] = flat[idx * CDIM + cc];
    }
    for (int e = tid; e < TQ * CDIM; e += 256) {
        int r  = e >> 8;
        int cc = e & 255;
        int idx = cidx_g[b * CKN + q0 + r];
        xc_s[r * AS + cc] = flat[idx * CDIM + cc];
    }
    for (int e = tid; e < 512; e += 256) pow_s[e] = pow_g[e];
    __syncthreads();

    // ---------------- GEMM1: xx -> g0 ----------------
    for (int nc = 0; nc < 2; ++nc) {
        float acc[8][8] = {};
        for (int k0 = 0; k0 < CDIM; k0 += KT) {
            for (int e = tid; e < 128 * KT; e += 256) {
                int n  = e >> 4;
                int kk = e & 15;
                w_s[n * WS + kk] = W0[(nc * 128 + n) * CDIM + k0 + kk];
            }
            __syncthreads();
#pragma unroll
            for (int kk = 0; kk < KT; kk += 4) {
                float4 wf[8];
#pragma unroll
                for (int j = 0; j < 8; ++j)
                    wf[j] = *(const float4*)&w_s[(tx + 16 * j) * WS + kk];
                float4 ap = *(const float4*)&xp_s[ty * AS + k0 + kk];
#pragma unroll
                for (int i = 0; i < 8; ++i) {
                    float4 cv = *(const float4*)&xc_s[i * AS + k0 + kk];
                    float d0 = ap.x - cv.x; d0 *= d0;
                    float d1 = ap.y - cv.y; d1 *= d1;
                    float d2 = ap.z - cv.z; d2 *= d2;
                    float d3 = ap.w - cv.w; d3 *= d3;
#pragma unroll
                    for (int j = 0; j < 8; ++j)
                        acc[i][j] += d0 * wf[j].x + d1 * wf[j].y +
                                     d2 * wf[j].z + d3 * wf[j].w;
                }
            }
            __syncthreads();
        }
#pragma unroll
        for (int i = 0; i < 8; ++i) {
#pragma unroll
            for (int j = 0; j < 8; ++j) {
                int n = nc * 128 + 16 * j + tx;
                g0_s[(ty * 8 + i) * AS + n] = fmaxf(acc[i][j] + b0[n], 0.0f);
            }
        }
    }
    __syncthreads();

    // ---------------- GEMM2: g0 -> g1, fused output layer ----------------
    float pout0[8] = {};
    float pout1[8] = {};
    for (int nc = 0; nc < 2; ++nc) {
        float acc[8][8] = {};
        for (int k0 = 0; k0 < CDIM; k0 += KT) {
            for (int e = tid; e < 128 * KT; e += 256) {
                int n  = e >> 4;
                int kk = e & 15;
                w_s[n * WS + kk] = W1[(nc * 128 + n) * CDIM + k0 + kk];
            }
            __syncthreads();
#pragma unroll
            for (int kk = 0; kk < KT; kk += 4) {
                float4 wf[8];
#pragma unroll
                for (int j = 0; j < 8; ++j)
                    wf[j] = *(const float4*)&w_s[(tx + 16 * j) * WS + kk];
#pragma unroll
                for (int i = 0; i < 8; ++i) {
                    float4 a = *(const float4*)&g0_s[(ty * 8 + i) * AS + k0 + kk];
#pragma unroll
                    for (int j = 0; j < 8; ++j)
                        acc[i][j] += a.x * wf[j].x + a.y * wf[j].y +
                                     a.z * wf[j].z + a.w * wf[j].w;
                }
            }
            __syncthreads();
        }
#pragma unroll
        for (int i = 0; i < 8; ++i) {
#pragma unroll
            for (int j = 0; j < 8; ++j) {
                int n = nc * 128 + 16 * j + tx;
                float g = fmaxf(acc[i][j] + b1[n], 0.0f);
                pout0[i] += pow_s[n] * g;
                pout1[i] += pow_s[256 + n] * g;
            }
        }
    }

    // reduce over tx (16 lanes, same warp segment)
#pragma unroll
    for (int off = 8; off; off >>= 1) {
#pragma unroll
        for (int i = 0; i < 8; ++i) {
            pout0[i] += __shfl_down_sync(0xffffffffu, pout0[i], off, 16);
            pout1[i] += __shfl_down_sync(0xffffffffu, pout1[i], off, 16);
        }
    }
    if (tx == 0) {
        int p = p0 + ty;
        float ob0 = pob[0], ob1 = pob[1];
#pragma unroll
        for (int i = 0; i < 8; ++i) {
            int q = q0 + i;
            out[((b * 2 + 0) * PKN + p) * CKN + q] = pout0[i] + ob0;
            out[((b * 2 + 1) * PKN + p) * CKN + q] = pout1[i] + ob1;
        }
    }
}

// ---------------------------------------------------------------------------
extern "C" void kernel_launch(void* const* d_in, const int* in_sizes, int n_in,
                              void* d_out, int out_size)
{
    (void)in_sizes; (void)n_in; (void)out_size;
    const float* x          = (const float*)d_in[0];
    const int*   pidx       = (const int*)  d_in[1];
    const int*   cidx       = (const int*)  d_in[2];
    const float* pre_w      = (const float*)d_in[3];
    const float* pre_b      = (const float*)d_in[4];
    const float* post_w     = (const float*)d_in[5];
    const float* post_b     = (const float*)d_in[6];
    const float* post_out_w = (const float*)d_in[7];
    const float* post_out_b = (const float*)d_in[8];
    float* out = (float*)d_out;

    const size_t smem_pre  = (size_t)(128 * AS + 128 * WS) * sizeof(float);
    const size_t smem_edge = (size_t)((TP + TQ + 128) * AS + 128 * WS + 512) * sizeof(float);

    cudaFuncSetAttribute(pre_layer_kernel<0>, cudaFuncAttributeMaxDynamicSharedMemorySize, (int)smem_pre);
    cudaFuncSetAttribute(pre_layer_kernel<1>, cudaFuncAttributeMaxDynamicSharedMemorySize, (int)smem_pre);
    cudaFuncSetAttribute(pre_layer_kernel<2>, cudaFuncAttributeMaxDynamicSharedMemorySize, (int)smem_pre);
    cudaFuncSetAttribute(edge_kernel,         cudaFuncAttributeMaxDynamicSharedMemorySize, (int)smem_edge);

    // pre_compare: 3 layers of 1x1 conv over 2048 pixels
    pre_layer_kernel<0><<<NPIX / 128, 256, smem_pre>>>(x, pre_w,                  pre_b);
    pre_layer_kernel<1><<<NPIX / 128, 256, smem_pre>>>(x, pre_w + 1 * 256 * 256,  pre_b + 256);
    pre_layer_kernel<2><<<NPIX / 128, 256, smem_pre>>>(x, pre_w + 2 * 256 * 256,  pre_b + 512);

    // fused gather + pairwise diff^2 + post_compare MLP
    dim3 grid(CKN / TQ, PKN / TP, 2);
    edge_kernel<<<grid, 256, smem_edge>>>(pidx, cidx,
                                          post_w,               post_b,
                                          post_w + 256 * 256,   post_b + 256,
                                          post_out_w, post_out_b, out);
}

// round 8
// speedup vs baseline: 1.0015x; 1.0015x over previous
#include <cuda_runtime.h>

// Problem constants
static const int CDIM = 256;
static const int HWSZ = 1024;   // 32*32
static const int NPIX = 2048;   // B*H*W
static const int PKN  = 256;
static const int CKN  = 256;

// Tiling
#define TP 16
#define TQ 8
#define AS 260   // padded stride for [.][256] fp32 smem rows
#define WS 20    // padded stride for W tile [128][16]
#define KT 16

// Scratch (allocation-free rule: __device__ globals)
__device__ float g_buf0[NPIX * CDIM];
__device__ float g_buf1[NPIX * CDIM];

// ---------------------------------------------------------------------------
// pre_compare layer: OUT[m][n] = act( sum_k A[m][k] * W[n][k] + b[n] )
// MODE 0: x -> buf0 (relu), MODE 1: buf0 -> buf1 (relu), MODE 2: buf1 -> buf0
// ---------------------------------------------------------------------------
template <int MODE>
__global__ void __launch_bounds__(256, 1)
pre_layer_kernel(const float* __restrict__ x,
                 const float* __restrict__ W,
                 const float* __restrict__ bias)
{
    extern __shared__ float sm[];
    float* A_s = sm;                 // [128][AS]
    float* w_s = A_s + 128 * AS;     // [128][WS]

    const int tid = threadIdx.x;
    const int tx = tid & 15;
    const int ty = tid >> 4;
    const int m0 = blockIdx.x * 128;

    const float* in = (MODE == 0) ? x : (MODE == 1 ? g_buf0 : g_buf1);
    float* outp     = (MODE == 1) ? g_buf1 : g_buf0;

    if (MODE == 0) {
        // x layout [B][C][HW]; pixel n = m0+m, consecutive m -> consecutive hw
        for (int e = tid; e < 128 * CDIM; e += 256) {
            int cc = e >> 7;            // 0..255
            int m  = e & 127;
            int n  = m0 + m;
            int b  = n >> 10;
            int hw = n & 1023;
            A_s[m * AS + cc] = in[(b * CDIM + cc) * HWSZ + hw];
        }
    } else {
        for (int e = tid; e < 128 * CDIM; e += 256) {
            int m  = e >> 8;
            int cc = e & 255;
            A_s[m * AS + cc] = in[(m0 + m) * CDIM + cc];
        }
    }
    __syncthreads();

    for (int nc = 0; nc < 2; ++nc) {
        float acc[8][8] = {};
        for (int k0 = 0; k0 < CDIM; k0 += KT) {
            for (int e = tid; e < 128 * KT; e += 256) {
                int n  = e >> 4;
                int kk = e & 15;
                w_s[n * WS + kk] = W[(nc * 128 + n) * CDIM + k0 + kk];
            }
            __syncthreads();
#pragma unroll
            for (int kk = 0; kk < KT; kk += 4) {
                float4 wf[8];
#pragma unroll
                for (int j = 0; j < 8; ++j)
                    wf[j] = *(const float4*)&w_s[(tx + 16 * j) * WS + kk];
#pragma unroll
                for (int i = 0; i < 8; ++i) {
                    float4 a = *(const float4*)&A_s[(ty * 8 + i) * AS + k0 + kk];
#pragma unroll
                    for (int j = 0; j < 8; ++j)
                        acc[i][j] += a.x * wf[j].x + a.y * wf[j].y +
                                     a.z * wf[j].z + a.w * wf[j].w;
                }
            }
            __syncthreads();
        }
#pragma unroll
        for (int i = 0; i < 8; ++i) {
#pragma unroll
            for (int j = 0; j < 8; ++j) {
                int n = nc * 128 + 16 * j + tx;
                float v = acc[i][j] + bias[n];
                if (MODE != 2) v = fmaxf(v, 0.0f);
                outp[(m0 + ty * 8 + i) * CDIM + n] = v;
            }
        }
    }
}

// ---------------------------------------------------------------------------
// Fused edge kernel:
//  per block: 16 p-rows x 8 q-rows (M=128 pairs)
//  GEMM1: g0 = relu(W0 . (xp-xc)^2 + b0)   (xx regenerated from smem)
//  GEMM2: g1 = relu(W1 . g0 + b1), fused out = pow . g1 + pob
// ---------------------------------------------------------------------------
__global__ void __launch_bounds__(256, 1)
edge_kernel(const int* __restrict__ pidx_g,
            const int* __restrict__ cidx_g,
            const float* __restrict__ W0, const float* __restrict__ b0,
            const float* __restrict__ W1, const float* __restrict__ b1,
            const float* __restrict__ pow_g, const float* __restrict__ pob,
            float* __restrict__ out)
{
    extern __shared__ float sm[];
    float* xp_s  = sm;                     // [TP][AS]
    float* xc_s  = xp_s + TP * AS;         // [TQ][AS]
    float* g0_s  = xc_s + TQ * AS;         // [128][AS]
    float* w_s   = g0_s + 128 * AS;        // [128][WS]
    float* pow_s = w_s + 128 * WS;         // [512]

    const int tid = threadIdx.x;
    const int tx = tid & 15;
    const int ty = tid >> 4;
    const int q0 = blockIdx.x * TQ;
    const int p0 = blockIdx.y * TP;
    const int b  = blockIdx.z;

    const float* flat = g_buf0;

    for (int e = tid; e < TP * CDIM; e += 256) {
        int r  = e >> 8;
        int cc = e & 255;
        int idx = pidx_g[b * PKN + p0 + r];
        xp_s[r * AS + cc] = flat[idx * CDIM + cc];
    }
    for (int e = tid; e < TQ * CDIM; e += 256) {
        int r  = e >> 8;
        int cc = e & 255;
        int idx = cidx_g[b * CKN + q0 + r];
        xc_s[r * AS + cc] = flat[idx * CDIM + cc];
    }
    for (int e = tid; e < 512; e += 256) pow_s[e] = pow_g[e];
    __syncthreads();

    // ---------------- GEMM1: xx -> g0 ----------------
    for (int nc = 0; nc < 2; ++nc) {
        float acc[8][8] = {};
        for (int k0 = 0; k0 < CDIM; k0 += KT) {
            for (int e = tid; e < 128 * KT; e += 256) {
                int n  = e >> 4;
                int kk = e & 15;
                w_s[n * WS + kk] = W0[(nc * 128 + n) * CDIM + k0 + kk];
            }
            __syncthreads();
#pragma unroll
            for (int kk = 0; kk < KT; kk += 4) {
                float4 wf[8];
#pragma unroll
                for (int j = 0; j < 8; ++j)
                    wf[j] = *(const float4*)&w_s[(tx + 16 * j) * WS + kk];
                float4 ap = *(const float4*)&xp_s[ty * AS + k0 + kk];
#pragma unroll
                for (int i = 0; i < 8; ++i) {
                    float4 cv = *(const float4*)&xc_s[i * AS + k0 + kk];
                    float d0 = ap.x - cv.x; d0 *= d0;
                    float d1 = ap.y - cv.y; d1 *= d1;
                    float d2 = ap.z - cv.z; d2 *= d2;
                    float d3 = ap.w - cv.w; d3 *= d3;
#pragma unroll
                    for (int j = 0; j < 8; ++j)
                        acc[i][j] += d0 * wf[j].x + d1 * wf[j].y +
                                     d2 * wf[j].z + d3 * wf[j].w;
                }
            }
            __syncthreads();
        }
#pragma unroll
        for (int i = 0; i < 8; ++i) {
#pragma unroll
            for (int j = 0; j < 8; ++j) {
                int n = nc * 128 + 16 * j + tx;
                g0_s[(ty * 8 + i) * AS + n] = fmaxf(acc[i][j] + b0[n], 0.0f);
            }
        }
    }
    __syncthreads();

    // ---------------- GEMM2: g0 -> g1, fused output layer ----------------
    float pout0[8] = {};
    float pout1[8] = {};
    for (int nc = 0; nc < 2; ++nc) {
        float acc[8][8] = {};
        for (int k0 = 0; k0 < CDIM; k0 += KT) {
            for (int e = tid; e < 128 * KT; e += 256) {
                int n  = e >> 4;
                int kk = e & 15;
                w_s[n * WS + kk] = W1[(nc * 128 + n) * CDIM + k0 + kk];
            }
            __syncthreads();
#pragma unroll
            for (int kk = 0; kk < KT; kk += 4) {
                float4 wf[8];
#pragma unroll
                for (int j = 0; j < 8; ++j)
                    wf[j] = *(const float4*)&w_s[(tx + 16 * j) * WS + kk];
#pragma unroll
                for (int i = 0; i < 8; ++i) {
                    float4 a = *(const float4*)&g0_s[(ty * 8 + i) * AS + k0 + kk];
#pragma unroll
                    for (int j = 0; j < 8; ++j)
                        acc[i][j] += a.x * wf[j].x + a.y * wf[j].y +
                                     a.z * wf[j].z + a.w * wf[j].w;
                }
            }
            __syncthreads();
        }
#pragma unroll
        for (int i = 0; i < 8; ++i) {
#pragma unroll
            for (int j = 0; j < 8; ++j) {
                int n = nc * 128 + 16 * j + tx;
                float g = fmaxf(acc[i][j] + b1[n], 0.0f);
                pout0[i] += pow_s[n] * g;
                pout1[i] += pow_s[256 + n] * g;
            }
        }
    }

    // reduce over tx (16 lanes, same warp segment)
#pragma unroll
    for (int off = 8; off; off >>= 1) {
#pragma unroll
        for (int i = 0; i < 8; ++i) {
            pout0[i] += __shfl_down_sync(0xffffffffu, pout0[i], off, 16);
            pout1[i] += __shfl_down_sync(0xffffffffu, pout1[i], off, 16);
        }
    }
    if (tx == 0) {
        int p = p0 + ty;
        float ob0 = pob[0], ob1 = pob[1];
#pragma unroll
        for (int i = 0; i < 8; ++i) {
            int q = q0 + i;
            out[((b * 2 + 0) * PKN + p) * CKN + q] = pout0[i] + ob0;
            out[((b * 2 + 1) * PKN + p) * CKN + q] = pout1[i] + ob1;
        }
    }
}

// ---------------------------------------------------------------------------
extern "C" void kernel_launch(void* const* d_in, const int* in_sizes, int n_in,
                              void* d_out, int out_size)
{
    (void)in_sizes; (void)n_in; (void)out_size;
    const float* x          = (const float*)d_in[0];
    const int*   pidx       = (const int*)  d_in[1];
    const int*   cidx       = (const int*)  d_in[2];
    const float* pre_w      = (const float*)d_in[3];
    const float* pre_b      = (const float*)d_in[4];
    const float* post_w     = (const float*)d_in[5];
    const float* post_b     = (const float*)d_in[6];
    const float* post_out_w = (const float*)d_in[7];
    const float* post_out_b = (const float*)d_in[8];
    float* out = (float*)d_out;

    const size_t smem_pre  = (size_t)(128 * AS + 128 * WS) * sizeof(float);
    const size_t smem_edge = (size_t)((TP + TQ + 128) * AS + 128 * WS + 512) * sizeof(float);

    cudaFuncSetAttribute(pre_layer_kernel<0>, cudaFuncAttributeMaxDynamicSharedMemorySize, (int)smem_pre);
    cudaFuncSetAttribute(pre_layer_kernel<1>, cudaFuncAttributeMaxDynamicSharedMemorySize, (int)smem_pre);
    cudaFuncSetAttribute(pre_layer_kernel<2>, cudaFuncAttributeMaxDynamicSharedMemorySize, (int)smem_pre);
    cudaFuncSetAttribute(edge_kernel,         cudaFuncAttributeMaxDynamicSharedMemorySize, (int)smem_edge);

    // pre_compare: 3 layers of 1x1 conv over 2048 pixels
    pre_layer_kernel<0><<<NPIX / 128, 256, smem_pre>>>(x, pre_w,                  pre_b);
    pre_layer_kernel<1><<<NPIX / 128, 256, smem_pre>>>(x, pre_w + 1 * 256 * 256,  pre_b + 256);
    pre_layer_kernel<2><<<NPIX / 128, 256, smem_pre>>>(x, pre_w + 2 * 256 * 256,  pre_b + 512);

    // fused gather + pairwise diff^2 + post_compare MLP
    dim3 grid(CKN / TQ, PKN / TP, 2);
    edge_kernel<<<grid, 256, smem_edge>>>(pidx, cidx,
                                          post_w,               post_b,
                                          post_w + 256 * 256,   post_b + 256,
                                          post_out_w, post_out_b, out);
}